// round 14
// baseline (speedup 1.0000x reference)
#include <cuda_runtime.h>
#include <cstdint>

#define LUT_D 33
#define NLUT (LUT_D * LUT_D * LUT_D)   // 35937
#define SPAD 1127                      // pad to 37064 = 9266*4 words (16B tiles); covers corner reads
#define NTOT (NLUT + SPAD)             // 37064
#define HW4C 518400                    // (1080*1920)/4, fixed by the problem shape

typedef unsigned long long ull;

// Packed LUT: R in bits [0:11), B in [11:21), G in [21:32). Stored as uint4 for
// guaranteed 16B alignment of the vectorized preamble copy.
__device__ uint4 g_lut_packed4[NTOT / 4];

__global__ void pack_lut_kernel(const float* __restrict__ lut) {
    int i = blockIdx.x * blockDim.x + threadIdx.x;
    if (i < NTOT) {
        int j = (i < NLUT) ? i : (NLUT - 1);
        float r = lut[j];
        float g = lut[NLUT + j];
        float b = lut[2 * NLUT + j];
        uint32_t qr = min(__float2uint_rn(fminf(fmaxf(r, 0.0f), 1.0f) * 2047.0f), 2047u);
        uint32_t qg = min(__float2uint_rn(fminf(fmaxf(g, 0.0f), 1.0f) * 2047.0f), 2047u);
        uint32_t qb = min(__float2uint_rn(fminf(fmaxf(b, 0.0f), 1.0f) * 1023.0f), 1023u);
        ((uint32_t*)g_lut_packed4)[i] = qr | (qb << 11) | (qg << 21);
    }
}

// ---- packed f32x2 helpers (sm_103a FFMA2/FADD2/FMUL2 via PTX) ----
__device__ __forceinline__ ull pk2(float lo, float hi) {
    ull r; asm("mov.b64 %0, {%1, %2};" : "=l"(r) : "f"(lo), "f"(hi)); return r;
}
__device__ __forceinline__ void unpk2(ull v, float& lo, float& hi) {
    asm("mov.b64 {%0, %1}, %2;" : "=f"(lo), "=f"(hi) : "l"(v));
}
__device__ __forceinline__ ull fma2(ull a, ull b, ull c) {
    ull d; asm("fma.rn.f32x2 %0, %1, %2, %3;" : "=l"(d) : "l"(a), "l"(b), "l"(c)); return d;
}
__device__ __forceinline__ ull add2(ull a, ull b) {
    ull d; asm("add.rn.f32x2 %0, %1, %2;" : "=l"(d) : "l"(a), "l"(b)); return d;
}
__device__ __forceinline__ ull mul2(ull a, ull b) {
    ull d; asm("mul.rn.f32x2 %0, %1, %2;" : "=l"(d) : "l"(a), "l"(b)); return d;
}

// Biased fixed-point extraction (value = 2^23 + field); bias removed at the end.
__device__ __forceinline__ float bR(uint32_t v) {          // 1 LOP3 (alu)
    return __uint_as_float((v & 2047u) | 0x4B000000u);
}
__device__ __forceinline__ float bB(uint32_t v) {          // IMAD.HI (fma pipe) + LOP3; field x4
    return __uint_as_float((__umulhi(v, 8388608u) & 0xFFCu) | 0x4B000000u);
}
__device__ __forceinline__ float bG(uint32_t v) {          // 1 SHF (funnel): (v>>21)|0x4B000000
    return __uint_as_float(__funnelshift_r(v, 0x96000u, 21));
}

struct P3 { float r, g, b; };

// Scalar accumulate + epilogue over 8 pre-loaded corner words.
__device__ __forceinline__ P3 accum_px(uint32_t v0, uint32_t v1, uint32_t v2, uint32_t v3,
                                       uint32_t v4, uint32_t v5, uint32_t v6, uint32_t v7,
                                       float fx, float w00, float w01, float w10, float w11) {
    float sr0 = 0.0f, sr1 = 0.0f, sg0 = 0.0f, sg1 = 0.0f, sb0 = 0.0f, sb1 = 0.0f;
#define ROW(a, b, w) {                                 \
    sr0 = fmaf((w), bR(a), sr0);                       \
    sr1 = fmaf((w), bR(b), sr1);                       \
    sg0 = fmaf((w), bG(a), sg0);                       \
    sg1 = fmaf((w), bG(b), sg1);                       \
    sb0 = fmaf((w), bB(a), sb0);                       \
    sb1 = fmaf((w), bB(b), sb1); }
    ROW(v0, v1, w00)
    ROW(v2, v3, w01)
    ROW(v4, v5, w10)
    ROW(v6, v7, w11)
#undef ROW
    P3 o;
    o.r = (fmaf(fx, sr1 - sr0, sr0) - 8388608.0f) * (1.0f / 2047.0f);
    o.g = (fmaf(fx, sg1 - sg0, sg0) - 8388608.0f) * (1.0f / 2047.0f);
    o.b = (fmaf(fx, sb1 - sb0, sb0) - 8388608.0f) * (1.0f / 4092.0f);  // B was x4
    return o;
}

// Prologue for one pixel pair: packed floor/frac + packed flat index.
__device__ __forceinline__ void prolog_pair(const uint32_t* __restrict__ s,
                                            ull cx2, ull cy2, ull cz2,
                                            const uint32_t*& spA, const uint32_t*& spB,
                                            ull& tx2, ull& ty2, ull& tz2) {
    const ull C32   = 0x4200000042000000ULL;  // {32, 32}
    const ull C33   = 0x4204000042040000ULL;  // {33, 33}
    const ull C1089 = 0x4488200044882000ULL;  // {1089, 1089}
    const ull CMH   = 0xBF000000BF000000ULL;  // {-0.5, -0.5}
    const ull CMAG  = 0x4B4000004B400000ULL;  // {1.5*2^23, .}
    const ull CNMG  = 0xCB400000CB400000ULL;  // {-1.5*2^23, .}
    const ull CM1   = 0xBF800000BF800000ULL;  // {-1, -1}

    ull mx2 = fma2(cx2, C32, CMH);
    ull my2 = fma2(cy2, C32, CMH);
    ull mz2 = fma2(cz2, C32, CMH);
    ull ux2 = add2(mx2, CMAG);
    ull uy2 = add2(my2, CMAG);
    ull uz2 = add2(mz2, CMAG);
    ull ex2 = add2(ux2, CNMG);
    ull ey2 = add2(uy2, CNMG);
    ull ez2 = add2(uz2, CNMG);
    tx2 = fma2(ex2, CM1, mx2);
    ty2 = fma2(ey2, CM1, my2);
    tz2 = fma2(ez2, CM1, mz2);

    ull idxf2 = fma2(ez2, C1089, fma2(ey2, C33, ex2));
    ull idxu2 = add2(idxf2, CMAG);
    float iAf, iBf;
    unpk2(idxu2, iAf, iBf);
    spA = s + (__float_as_int(iAf) & 0x3FFFF);
    spB = s + (__float_as_int(iBf) & 0x3FFFF);
}

// Whole iteration (4 pixels): both prologues, then ALL 32 LDS back-to-back,
// then weights (overlapping LDS latency), then math.
__device__ __forceinline__ void do_quad(const uint32_t* __restrict__ s,
                                        ull cx0, ull cy0, ull cz0,
                                        ull cx1, ull cy1, ull cz1,
                                        P3& o0, P3& o1, P3& o2, P3& o3) {
    const ull CM1 = 0xBF800000BF800000ULL;  // {-1, -1}
    const ull CH  = 0x3F0000003F000000ULL;  // {0.5, 0.5}

    const uint32_t *sp0, *sp1, *sp2, *sp3;
    ull tx0, ty0, tz0, tx1, ty1, tz1;
    prolog_pair(s, cx0, cy0, cz0, sp0, sp1, tx0, ty0, tz0);
    prolog_pair(s, cx1, cy1, cz1, sp2, sp3, tx1, ty1, tz1);

    // 32 shared loads, one burst.
    uint32_t A0 = sp0[0],    A1 = sp0[1],    A2 = sp0[33],   A3 = sp0[34];
    uint32_t A4 = sp0[1089], A5 = sp0[1090], A6 = sp0[1122], A7 = sp0[1123];
    uint32_t B0 = sp1[0],    B1 = sp1[1],    B2 = sp1[33],   B3 = sp1[34];
    uint32_t B4 = sp1[1089], B5 = sp1[1090], B6 = sp1[1122], B7 = sp1[1123];
    uint32_t C0 = sp2[0],    C1 = sp2[1],    C2 = sp2[33],   C3 = sp2[34];
    uint32_t C4 = sp2[1089], C5 = sp2[1090], C6 = sp2[1122], C7 = sp2[1123];
    uint32_t D0 = sp3[0],    D1 = sp3[1],    D2 = sp3[33],   D3 = sp3[34];
    uint32_t D4 = sp3[1089], D5 = sp3[1090], D6 = sp3[1122], D7 = sp3[1123];

    // Weights for both pairs (packed), overlapping the LDS latency.
    ull fxA = add2(tx0, CH);
    ull fyA = add2(ty0, CH), gyA = fma2(ty0, CM1, CH);
    ull fzA = add2(tz0, CH), gzA = fma2(tz0, CM1, CH);
    ull w00A = mul2(gzA, gyA), w01A = mul2(gzA, fyA);
    ull w10A = mul2(fzA, gyA), w11A = mul2(fzA, fyA);

    ull fxB = add2(tx1, CH);
    ull fyB = add2(ty1, CH), gyB = fma2(ty1, CM1, CH);
    ull fzB = add2(tz1, CH), gzB = fma2(tz1, CM1, CH);
    ull w00B = mul2(gzB, gyB), w01B = mul2(gzB, fyB);
    ull w10B = mul2(fzB, gyB), w11B = mul2(fzB, fyB);

    float fxa, fxb, w00a, w00b, w01a, w01b, w10a, w10b, w11a, w11b;
    unpk2(fxA, fxa, fxb);
    unpk2(w00A, w00a, w00b);
    unpk2(w01A, w01a, w01b);
    unpk2(w10A, w10a, w10b);
    unpk2(w11A, w11a, w11b);
    o0 = accum_px(A0, A1, A2, A3, A4, A5, A6, A7, fxa, w00a, w01a, w10a, w11a);
    o1 = accum_px(B0, B1, B2, B3, B4, B5, B6, B7, fxb, w00b, w01b, w10b, w11b);

    float fxc, fxd, w00c, w00d, w01c, w01d, w10c, w10d, w11c, w11d;
    unpk2(fxB, fxc, fxd);
    unpk2(w00B, w00c, w00d);
    unpk2(w01B, w01c, w01d);
    unpk2(w10B, w10c, w10d);
    unpk2(w11B, w11c, w11d);
    o2 = accum_px(C0, C1, C2, C3, C4, C5, C6, C7, fxc, w00c, w01c, w10c, w11c);
    o3 = accum_px(D0, D1, D2, D3, D4, D5, D6, D7, fxd, w00d, w01d, w10d, w11d);
}

__global__ __launch_bounds__(1024, 1)
void trilut_kernel(const float* __restrict__ img,
                   float* __restrict__ out,
                   int total4) {
    extern __shared__ uint32_t s_lut[];
    {   // vectorized table preamble: 16B tiles
        uint4* s4 = (uint4*)s_lut;
        for (int i = threadIdx.x; i < NTOT / 4; i += 1024)
            s4[i] = g_lut_packed4[i];
    }
    __syncthreads();

    const float4* img4 = (const float4*)img;
    float4* out4 = (float4*)out;
    int stride = gridDim.x * 1024;
    int tid0 = blockIdx.x * 1024 + threadIdx.x;

    for (int q = tid0; q < total4; q += stride) {
        unsigned b = (unsigned)q / HW4C;               // compile-time divisor -> mul.hi
        int p = q - (int)b * HW4C;
        int base = (int)b * 3 * HW4C;                  // in float4 units

        // Prefetch NEXT iteration's lines a full body (~700 cyc) ahead of their
        // demand loads, so next loop-top LDGs hit L2.
        int qn = q + stride;
        if (qn < total4) {
            unsigned bn = (unsigned)qn / HW4C;
            int pn = qn - (int)bn * HW4C;
            const float4* a = img4 + ((int)bn * 3 * HW4C + pn);
            asm volatile("prefetch.global.L2 [%0];" :: "l"(a));
            asm volatile("prefetch.global.L2 [%0];" :: "l"(a + HW4C));
            asm volatile("prefetch.global.L2 [%0];" :: "l"(a + 2 * HW4C));
        }

        float4 R = img4[base + p];
        float4 G = img4[base + HW4C + p];
        float4 B = img4[base + 2 * HW4C + p];

        P3 o0, o1, o2, o3;
        do_quad(s_lut,
                pk2(R.x, R.y), pk2(G.x, G.y), pk2(B.x, B.y),
                pk2(R.z, R.w), pk2(G.z, G.w), pk2(B.z, B.w),
                o0, o1, o2, o3);

        out4[base + p]            = make_float4(o0.r, o1.r, o2.r, o3.r);
        out4[base + HW4C + p]     = make_float4(o0.g, o1.g, o2.g, o3.g);
        out4[base + 2 * HW4C + p] = make_float4(o0.b, o1.b, o2.b, o3.b);
    }
}

extern "C" void kernel_launch(void* const* d_in, const int* in_sizes, int n_in,
                              void* d_out, int out_size) {
    const float* lut = (const float*)d_in[0];
    const float* img = (const float*)d_in[1];
    float* out = (float*)d_out;

    int nimg = in_sizes[1];
    int nbatch = nimg / (3 * 4 * HW4C);  // 4
    int total4 = nbatch * HW4C;

    pack_lut_kernel<<<(NTOT + 255) / 256, 256>>>(lut);

    int smem = NTOT * (int)sizeof(uint32_t);  // 148,256 B
    cudaFuncSetAttribute(trilut_kernel,
                         cudaFuncAttributeMaxDynamicSharedMemorySize, smem);

    int dev = 0;
    cudaGetDevice(&dev);
    int nsm = 148;
    cudaDeviceGetAttribute(&nsm, cudaDevAttrMultiProcessorCount, dev);

    trilut_kernel<<<nsm, 1024, smem>>>(img, out, total4);
}

// round 15
// speedup vs baseline: 1.0421x; 1.0421x over previous
#include <cuda_runtime.h>
#include <cstdint>

#define LUT_D 33
#define NLUT (LUT_D * LUT_D * LUT_D)   // 35937
#define SPAD 1127                      // pad to 37064 words (16B-tileable); covers weight-0 corner reads
#define NTOT (NLUT + SPAD)             // 37064
#define HW4C 518400                    // (1080*1920)/4, fixed by the problem shape

typedef unsigned long long ull;

// Packed LUT: R in bits [0:11), B in [11:21), G in [21:32). uint4 storage for
// 16B-aligned vectorized preamble copy.
__device__ uint4 g_lut_packed4[NTOT / 4];

__global__ void pack_lut_kernel(const float* __restrict__ lut) {
    int i = blockIdx.x * blockDim.x + threadIdx.x;
    if (i < NTOT) {
        int j = (i < NLUT) ? i : (NLUT - 1);
        float r = lut[j];
        float g = lut[NLUT + j];
        float b = lut[2 * NLUT + j];
        uint32_t qr = min(__float2uint_rn(fminf(fmaxf(r, 0.0f), 1.0f) * 2047.0f), 2047u);
        uint32_t qg = min(__float2uint_rn(fminf(fmaxf(g, 0.0f), 1.0f) * 2047.0f), 2047u);
        uint32_t qb = min(__float2uint_rn(fminf(fmaxf(b, 0.0f), 1.0f) * 1023.0f), 1023u);
        ((uint32_t*)g_lut_packed4)[i] = qr | (qb << 11) | (qg << 21);
    }
}

// ---- packed f32x2 helpers (sm_103a FFMA2/FADD2/FMUL2 via PTX) ----
__device__ __forceinline__ ull pk2(float lo, float hi) {
    ull r; asm("mov.b64 %0, {%1, %2};" : "=l"(r) : "f"(lo), "f"(hi)); return r;
}
__device__ __forceinline__ void unpk2(ull v, float& lo, float& hi) {
    asm("mov.b64 {%0, %1}, %2;" : "=f"(lo), "=f"(hi) : "l"(v));
}
__device__ __forceinline__ ull fma2(ull a, ull b, ull c) {
    ull d; asm("fma.rn.f32x2 %0, %1, %2, %3;" : "=l"(d) : "l"(a), "l"(b), "l"(c)); return d;
}
__device__ __forceinline__ ull add2(ull a, ull b) {
    ull d; asm("add.rn.f32x2 %0, %1, %2;" : "=l"(d) : "l"(a), "l"(b)); return d;
}
__device__ __forceinline__ ull mul2(ull a, ull b) {
    ull d; asm("mul.rn.f32x2 %0, %1, %2;" : "=l"(d) : "l"(a), "l"(b)); return d;
}

// Biased fixed-point extraction (value = 2^23 + field); bias removed at the end.
__device__ __forceinline__ float bR(uint32_t v) {          // 1 LOP3 (alu)
    return __uint_as_float((v & 2047u) | 0x4B000000u);
}
__device__ __forceinline__ float bB(uint32_t v) {          // IMAD.HI (fma pipe) + LOP3; field x4
    return __uint_as_float((__umulhi(v, 8388608u) & 0xFFCu) | 0x4B000000u);
}
__device__ __forceinline__ float bG(uint32_t v) {          // 1 SHF (funnel): (v>>21)|0x4B000000
    return __uint_as_float(__funnelshift_r(v, 0x96000u, 21));
}

struct P3 { float r, g, b; };

// Scalar accumulate + epilogue over 8 pre-loaded corner words.
__device__ __forceinline__ P3 accum_px(uint32_t v0, uint32_t v1, uint32_t v2, uint32_t v3,
                                       uint32_t v4, uint32_t v5, uint32_t v6, uint32_t v7,
                                       float fx, float w00, float w01, float w10, float w11) {
    float sr0 = 0.0f, sr1 = 0.0f, sg0 = 0.0f, sg1 = 0.0f, sb0 = 0.0f, sb1 = 0.0f;
#define ROW(a, b, w) {                                 \
    sr0 = fmaf((w), bR(a), sr0);                       \
    sr1 = fmaf((w), bR(b), sr1);                       \
    sg0 = fmaf((w), bG(a), sg0);                       \
    sg1 = fmaf((w), bG(b), sg1);                       \
    sb0 = fmaf((w), bB(a), sb0);                       \
    sb1 = fmaf((w), bB(b), sb1); }
    ROW(v0, v1, w00)
    ROW(v2, v3, w01)
    ROW(v4, v5, w10)
    ROW(v6, v7, w11)
#undef ROW
    P3 o;
    o.r = (fmaf(fx, sr1 - sr0, sr0) - 8388608.0f) * (1.0f / 2047.0f);
    o.g = (fmaf(fx, sg1 - sg0, sg0) - 8388608.0f) * (1.0f / 2047.0f);
    o.b = (fmaf(fx, sb1 - sb0, sb0) - 8388608.0f) * (1.0f / 4092.0f);  // B was x4
    return o;
}

// Pixel pair: packed prologue + packed flat index; ALL 16 LDS issued before
// any accumulation math (pixel B's loads hide pixel A's math latency).
__device__ __forceinline__ void do_pair(const uint32_t* __restrict__ s,
                                        ull cx2, ull cy2, ull cz2,
                                        P3& oA, P3& oB) {
    const ull C32   = 0x4200000042000000ULL;  // {32, 32}
    const ull C33   = 0x4204000042040000ULL;  // {33, 33}
    const ull C1089 = 0x4488200044882000ULL;  // {1089, 1089}
    const ull CMH   = 0xBF000000BF000000ULL;  // {-0.5, -0.5}
    const ull CMAG  = 0x4B4000004B400000ULL;  // {1.5*2^23, .}
    const ull CNMG  = 0xCB400000CB400000ULL;  // {-1.5*2^23, .}
    const ull CM1   = 0xBF800000BF800000ULL;  // {-1, -1}
    const ull CH    = 0x3F0000003F000000ULL;  // {0.5, 0.5}

    // m = 32c - 0.5 ; u = RN(m + MAGIC) => floor(32c) exact in e* ; t = frac - 0.5
    ull mx2 = fma2(cx2, C32, CMH);
    ull my2 = fma2(cy2, C32, CMH);
    ull mz2 = fma2(cz2, C32, CMH);
    ull ux2 = add2(mx2, CMAG);
    ull uy2 = add2(my2, CMAG);
    ull uz2 = add2(mz2, CMAG);
    ull ex2 = add2(ux2, CNMG);
    ull ey2 = add2(uy2, CNMG);
    ull ez2 = add2(uz2, CNMG);
    ull tx2 = fma2(ex2, CM1, mx2);
    ull ty2 = fma2(ey2, CM1, my2);
    ull tz2 = fma2(ez2, CM1, mz2);

    // flat index = (ez*33 + ey)*33 + ex  (exact in fp32, < 2^18)
    ull idxf2 = fma2(ez2, C1089, fma2(ey2, C33, ex2));
    ull idxu2 = add2(idxf2, CMAG);
    float iAf, iBf;
    unpk2(idxu2, iAf, iBf);
    const uint32_t* spA = s + (__float_as_int(iAf) & 0x3FFFF);
    const uint32_t* spB = s + (__float_as_int(iBf) & 0x3FFFF);

    // Issue ALL 16 shared loads before dependent math.
    uint32_t A0 = spA[0],    A1 = spA[1];
    uint32_t A2 = spA[33],   A3 = spA[34];
    uint32_t A4 = spA[1089], A5 = spA[1090];
    uint32_t A6 = spA[1122], A7 = spA[1123];
    uint32_t B0 = spB[0],    B1 = spB[1];
    uint32_t B2 = spB[33],   B3 = spB[34];
    uint32_t B4 = spB[1089], B5 = spB[1090];
    uint32_t B6 = spB[1122], B7 = spB[1123];

    // Weights (packed math, scalar unpack) — overlaps the LDS latency.
    ull fx2 = add2(tx2, CH);
    ull fy2 = add2(ty2, CH);
    ull gy2 = fma2(ty2, CM1, CH);
    ull fz2 = add2(tz2, CH);
    ull gz2 = fma2(tz2, CM1, CH);
    ull w00_2 = mul2(gz2, gy2);
    ull w01_2 = mul2(gz2, fy2);
    ull w10_2 = mul2(fz2, gy2);
    ull w11_2 = mul2(fz2, fy2);

    float fxa, fxb, w00a, w00b, w01a, w01b, w10a, w10b, w11a, w11b;
    unpk2(fx2, fxa, fxb);
    unpk2(w00_2, w00a, w00b);
    unpk2(w01_2, w01a, w01b);
    unpk2(w10_2, w10a, w10b);
    unpk2(w11_2, w11a, w11b);

    oA = accum_px(A0, A1, A2, A3, A4, A5, A6, A7, fxa, w00a, w01a, w10a, w11a);
    oB = accum_px(B0, B1, B2, B3, B4, B5, B6, B7, fxb, w00b, w01b, w10b, w11b);
}

__global__ __launch_bounds__(1024, 1)
void trilut_kernel(const float* __restrict__ img,
                   float* __restrict__ out,
                   int total4) {
    extern __shared__ uint32_t s_lut[];

    const float4* img4 = (const float4*)img;
    float4* out4 = (float4*)out;
    int stride = gridDim.x * 1024;
    int tid0 = blockIdx.x * 1024 + threadIdx.x;

    // Issue the FIRST iteration's image loads before the table copy: their
    // cold-DRAM latency overlaps the 148KB preamble instead of following it.
    int q = tid0;
    bool act = q < total4;
    unsigned b = (unsigned)q / HW4C;
    int p = q - (int)b * HW4C;
    int base = (int)b * 3 * HW4C;
    float4 R, G, B;
    if (act) {
        R = __ldcs(&img4[base + p]);
        G = __ldcs(&img4[base + HW4C + p]);
        B = __ldcs(&img4[base + 2 * HW4C + p]);
    }

    {   // vectorized table preamble: 16B tiles
        uint4* s4 = (uint4*)s_lut;
        for (int i = threadIdx.x; i < NTOT / 4; i += 1024)
            s4[i] = g_lut_packed4[i];
    }
    __syncthreads();

    if (!act) return;

    // Software pipeline: iteration n+1's image loads are issued BEFORE
    // iteration n's gather/math, hiding the DRAM latency under ~300 instrs.
    for (;;) {
        int qn = q + stride;
        bool more = qn < total4;
        int qe = more ? qn : q;                        // branchless: reload current on last iter
        unsigned bn = (unsigned)qe / HW4C;             // compile-time divisor -> mul.hi
        int pn = qe - (int)bn * HW4C;
        int basen = (int)bn * 3 * HW4C;
        float4 Rn = __ldcs(&img4[basen + pn]);
        float4 Gn = __ldcs(&img4[basen + HW4C + pn]);
        float4 Bn = __ldcs(&img4[basen + 2 * HW4C + pn]);

        P3 o0, o1, o2, o3;
        do_pair(s_lut, pk2(R.x, R.y), pk2(G.x, G.y), pk2(B.x, B.y), o0, o1);
        do_pair(s_lut, pk2(R.z, R.w), pk2(G.z, G.w), pk2(B.z, B.w), o2, o3);

        __stcs(&out4[base + p],            make_float4(o0.r, o1.r, o2.r, o3.r));
        __stcs(&out4[base + HW4C + p],     make_float4(o0.g, o1.g, o2.g, o3.g));
        __stcs(&out4[base + 2 * HW4C + p], make_float4(o0.b, o1.b, o2.b, o3.b));

        if (!more) break;
        q = qn; p = pn; base = basen;
        R = Rn; G = Gn; B = Bn;
    }
}

extern "C" void kernel_launch(void* const* d_in, const int* in_sizes, int n_in,
                              void* d_out, int out_size) {
    const float* lut = (const float*)d_in[0];
    const float* img = (const float*)d_in[1];
    float* out = (float*)d_out;

    int nimg = in_sizes[1];
    int nbatch = nimg / (3 * 4 * HW4C);  // 4
    int total4 = nbatch * HW4C;

    pack_lut_kernel<<<(NTOT + 255) / 256, 256>>>(lut);

    int smem = NTOT * (int)sizeof(uint32_t);  // 148,256 B
    cudaFuncSetAttribute(trilut_kernel,
                         cudaFuncAttributeMaxDynamicSharedMemorySize, smem);

    int dev = 0;
    cudaGetDevice(&dev);
    int nsm = 148;
    cudaDeviceGetAttribute(&nsm, cudaDevAttrMultiProcessorCount, dev);

    trilut_kernel<<<nsm, 1024, smem>>>(img, out, total4);
}

// round 16
// speedup vs baseline: 1.0570x; 1.0142x over previous
#include <cuda_runtime.h>
#include <cstdint>

#define LUT_D 33
#define NLUT (LUT_D * LUT_D * LUT_D)   // 35937
#define SPAD 1127                      // pad to 37064 words (16B-tileable); covers weight-0 corner reads
#define NTOT (NLUT + SPAD)             // 37064
#define HW4C 518400                    // (1080*1920)/4, fixed by the problem shape

typedef unsigned long long ull;

// Packed LUT: R in bits [0:11), B in [11:21), G in [21:32). uint4 storage for
// 16B-aligned vectorized preamble copy.
__device__ uint4 g_lut_packed4[NTOT / 4];

__global__ void pack_lut_kernel(const float* __restrict__ lut) {
    int i = blockIdx.x * blockDim.x + threadIdx.x;
    if (i < NTOT) {
        int j = (i < NLUT) ? i : (NLUT - 1);
        float r = lut[j];
        float g = lut[NLUT + j];
        float b = lut[2 * NLUT + j];
        uint32_t qr = min(__float2uint_rn(fminf(fmaxf(r, 0.0f), 1.0f) * 2047.0f), 2047u);
        uint32_t qg = min(__float2uint_rn(fminf(fmaxf(g, 0.0f), 1.0f) * 2047.0f), 2047u);
        uint32_t qb = min(__float2uint_rn(fminf(fmaxf(b, 0.0f), 1.0f) * 1023.0f), 1023u);
        ((uint32_t*)g_lut_packed4)[i] = qr | (qb << 11) | (qg << 21);
    }
}

// ---- packed f32x2 helpers (sm_103a FFMA2/FADD2/FMUL2 via PTX) ----
__device__ __forceinline__ ull pk2(float lo, float hi) {
    ull r; asm("mov.b64 %0, {%1, %2};" : "=l"(r) : "f"(lo), "f"(hi)); return r;
}
__device__ __forceinline__ void unpk2(ull v, float& lo, float& hi) {
    asm("mov.b64 {%0, %1}, %2;" : "=f"(lo), "=f"(hi) : "l"(v));
}
__device__ __forceinline__ ull fma2(ull a, ull b, ull c) {
    ull d; asm("fma.rn.f32x2 %0, %1, %2, %3;" : "=l"(d) : "l"(a), "l"(b), "l"(c)); return d;
}
__device__ __forceinline__ ull add2(ull a, ull b) {
    ull d; asm("add.rn.f32x2 %0, %1, %2;" : "=l"(d) : "l"(a), "l"(b)); return d;
}
__device__ __forceinline__ ull mul2(ull a, ull b) {
    ull d; asm("mul.rn.f32x2 %0, %1, %2;" : "=l"(d) : "l"(a), "l"(b)); return d;
}

// Biased fixed-point extraction (value = 2^23 + field); bias removed at the end.
__device__ __forceinline__ float bR(uint32_t v) {          // 1 LOP3 (alu)
    return __uint_as_float((v & 2047u) | 0x4B000000u);
}
__device__ __forceinline__ float bB(uint32_t v) {          // IMAD.HI (fma pipe) + LOP3; field x4
    return __uint_as_float((__umulhi(v, 8388608u) & 0xFFCu) | 0x4B000000u);
}
__device__ __forceinline__ float bG(uint32_t v) {          // 1 SHF (funnel): (v>>21)|0x4B000000
    return __uint_as_float(__funnelshift_r(v, 0x96000u, 21));
}

struct P3 { float r, g, b; };

// Scalar accumulate + epilogue over 8 pre-loaded corner words.
// Epilogue fused: (x - 2^23) * s  ==  fmaf(x, s, -2^23*s)   (1 op instead of 2)
__device__ __forceinline__ P3 accum_px(uint32_t v0, uint32_t v1, uint32_t v2, uint32_t v3,
                                       uint32_t v4, uint32_t v5, uint32_t v6, uint32_t v7,
                                       float fx, float w00, float w01, float w10, float w11) {
    float sr0 = 0.0f, sr1 = 0.0f, sg0 = 0.0f, sg1 = 0.0f, sb0 = 0.0f, sb1 = 0.0f;
#define ROW(a, b, w) {                                 \
    sr0 = fmaf((w), bR(a), sr0);                       \
    sr1 = fmaf((w), bR(b), sr1);                       \
    sg0 = fmaf((w), bG(a), sg0);                       \
    sg1 = fmaf((w), bG(b), sg1);                       \
    sb0 = fmaf((w), bB(a), sb0);                       \
    sb1 = fmaf((w), bB(b), sb1); }
    ROW(v0, v1, w00)
    ROW(v2, v3, w01)
    ROW(v4, v5, w10)
    ROW(v6, v7, w11)
#undef ROW
    const float S11 = 1.0f / 2047.0f;
    const float S10 = 1.0f / 4092.0f;                  // B was x4
    const float K11 = -8388608.0f / 2047.0f;
    const float K10 = -8388608.0f / 4092.0f;
    P3 o;
    o.r = fmaf(fmaf(fx, sr1 - sr0, sr0), S11, K11);
    o.g = fmaf(fmaf(fx, sg1 - sg0, sg0), S11, K11);
    o.b = fmaf(fmaf(fx, sb1 - sb0, sb0), S10, K10);
    return o;
}

// Pixel pair: packed prologue + packed flat index; ALL 16 LDS issued before
// any accumulation math (pixel B's loads hide pixel A's math latency).
__device__ __forceinline__ void do_pair(const uint32_t* __restrict__ s,
                                        ull cx2, ull cy2, ull cz2,
                                        P3& oA, P3& oB) {
    const ull C32   = 0x4200000042000000ULL;  // {32, 32}
    const ull C33   = 0x4204000042040000ULL;  // {33, 33}
    const ull C1089 = 0x4488200044882000ULL;  // {1089, 1089}
    const ull CMH   = 0xBF000000BF000000ULL;  // {-0.5, -0.5}
    const ull CMAG  = 0x4B4000004B400000ULL;  // {1.5*2^23, .}
    const ull CNMG  = 0xCB400000CB400000ULL;  // {-1.5*2^23, .}
    const ull CM1   = 0xBF800000BF800000ULL;  // {-1, -1}
    const ull CH    = 0x3F0000003F000000ULL;  // {0.5, 0.5}

    // m = 32c - 0.5 ; u = RN(m + MAGIC) => floor(32c) exact in e* ; t = frac - 0.5
    ull mx2 = fma2(cx2, C32, CMH);
    ull my2 = fma2(cy2, C32, CMH);
    ull mz2 = fma2(cz2, C32, CMH);
    ull ux2 = add2(mx2, CMAG);
    ull uy2 = add2(my2, CMAG);
    ull uz2 = add2(mz2, CMAG);
    ull ex2 = add2(ux2, CNMG);
    ull ey2 = add2(uy2, CNMG);
    ull ez2 = add2(uz2, CNMG);
    ull tx2 = fma2(ex2, CM1, mx2);
    ull ty2 = fma2(ey2, CM1, my2);
    ull tz2 = fma2(ez2, CM1, mz2);

    // flat index = (ez*33 + ey)*33 + ex  (exact in fp32, < 2^18)
    ull idxf2 = fma2(ez2, C1089, fma2(ey2, C33, ex2));
    ull idxu2 = add2(idxf2, CMAG);
    float iAf, iBf;
    unpk2(idxu2, iAf, iBf);
    const uint32_t* spA = s + (__float_as_int(iAf) & 0x3FFFF);
    const uint32_t* spB = s + (__float_as_int(iBf) & 0x3FFFF);

    // Issue ALL 16 shared loads before dependent math.
    uint32_t A0 = spA[0],    A1 = spA[1];
    uint32_t A2 = spA[33],   A3 = spA[34];
    uint32_t A4 = spA[1089], A5 = spA[1090];
    uint32_t A6 = spA[1122], A7 = spA[1123];
    uint32_t B0 = spB[0],    B1 = spB[1];
    uint32_t B2 = spB[33],   B3 = spB[34];
    uint32_t B4 = spB[1089], B5 = spB[1090];
    uint32_t B6 = spB[1122], B7 = spB[1123];

    // Weights (packed math, scalar unpack) — overlaps the LDS latency.
    ull fx2 = add2(tx2, CH);
    ull fy2 = add2(ty2, CH);
    ull gy2 = fma2(ty2, CM1, CH);
    ull fz2 = add2(tz2, CH);
    ull gz2 = fma2(tz2, CM1, CH);
    ull w00_2 = mul2(gz2, gy2);
    ull w01_2 = mul2(gz2, fy2);
    ull w10_2 = mul2(fz2, gy2);
    ull w11_2 = mul2(fz2, fy2);

    float fxa, fxb, w00a, w00b, w01a, w01b, w10a, w10b, w11a, w11b;
    unpk2(fx2, fxa, fxb);
    unpk2(w00_2, w00a, w00b);
    unpk2(w01_2, w01a, w01b);
    unpk2(w10_2, w10a, w10b);
    unpk2(w11_2, w11a, w11b);

    oA = accum_px(A0, A1, A2, A3, A4, A5, A6, A7, fxa, w00a, w01a, w10a, w11a);
    oB = accum_px(B0, B1, B2, B3, B4, B5, B6, B7, fxb, w00b, w01b, w10b, w11b);
}

__global__ __launch_bounds__(1024, 1)
void trilut_kernel(const float* __restrict__ img,
                   float* __restrict__ out,
                   int total4) {
    extern __shared__ uint32_t s_lut[];
    {   // vectorized table preamble: 16B tiles
        uint4* s4 = (uint4*)s_lut;
        for (int i = threadIdx.x; i < NTOT / 4; i += 1024)
            s4[i] = g_lut_packed4[i];
    }
    __syncthreads();

    const float4* img4 = (const float4*)img;
    float4* out4 = (float4*)out;
    int stride = gridDim.x * 1024;
    int tid0 = blockIdx.x * 1024 + threadIdx.x;

    // Software pipeline: iteration n+1's image loads are issued BEFORE
    // iteration n's gather/math, hiding the DRAM latency under ~300 instrs.
    int q = tid0;
    if (q >= total4) return;

    unsigned b0 = (unsigned)q / HW4C;                  // once, at entry
    int p = q - (int)b0 * HW4C;
    int base = (int)b0 * 3 * HW4C;
    float4 R = img4[base + p];
    float4 G = img4[base + HW4C + p];
    float4 B = img4[base + 2 * HW4C + p];

    for (;;) {
        int qn = q + stride;
        bool more = qn < total4;
        // Incremental (p, base): stride < HW4C, so at most one wrap per step.
        int pn = p + stride;
        int basen = base;
        if (pn >= HW4C) { pn -= HW4C; basen += 3 * HW4C; }
        int pe = more ? pn : p;                        // branchless: reload current on last iter
        int be = more ? basen : base;
        float4 Rn = img4[be + pe];
        float4 Gn = img4[be + HW4C + pe];
        float4 Bn = img4[be + 2 * HW4C + pe];

        P3 o0, o1, o2, o3;
        do_pair(s_lut, pk2(R.x, R.y), pk2(G.x, G.y), pk2(B.x, B.y), o0, o1);
        do_pair(s_lut, pk2(R.z, R.w), pk2(G.z, G.w), pk2(B.z, B.w), o2, o3);

        out4[base + p]            = make_float4(o0.r, o1.r, o2.r, o3.r);
        out4[base + HW4C + p]     = make_float4(o0.g, o1.g, o2.g, o3.g);
        out4[base + 2 * HW4C + p] = make_float4(o0.b, o1.b, o2.b, o3.b);

        if (!more) break;
        q = qn; p = pn; base = basen;
        R = Rn; G = Gn; B = Bn;
    }
}

extern "C" void kernel_launch(void* const* d_in, const int* in_sizes, int n_in,
                              void* d_out, int out_size) {
    const float* lut = (const float*)d_in[0];
    const float* img = (const float*)d_in[1];
    float* out = (float*)d_out;

    int nimg = in_sizes[1];
    int nbatch = nimg / (3 * 4 * HW4C);  // 4
    int total4 = nbatch * HW4C;

    pack_lut_kernel<<<(NTOT + 255) / 256, 256>>>(lut);

    int smem = NTOT * (int)sizeof(uint32_t);  // 148,256 B
    cudaFuncSetAttribute(trilut_kernel,
                         cudaFuncAttributeMaxDynamicSharedMemorySize, smem);

    int dev = 0;
    cudaGetDevice(&dev);
    int nsm = 148;
    cudaDeviceGetAttribute(&nsm, cudaDevAttrMultiProcessorCount, dev);

    trilut_kernel<<<nsm, 1024, smem>>>(img, out, total4);
}